// round 1
// baseline (speedup 1.0000x reference)
#include <cuda_runtime.h>

#define NQ 10
#define NGEN 4
#define QD 6
#define BATCH 1024

// Precomputed (cos(a/2), sin(a/2)) tables
__device__ float2 g_cs_noise[BATCH * NQ];
__device__ float2 g_cs_w[NGEN * QD * NQ];

__global__ void prep_kernel(const float* __restrict__ noise,
                            const float* __restrict__ qp) {
    int t = blockIdx.x * blockDim.x + threadIdx.x;
    if (t < BATCH * NQ) {
        float s, c;
        sincosf(0.5f * noise[t], &s, &c);
        g_cs_noise[t] = make_float2(c, s);
    } else if (t < BATCH * NQ + NGEN * QD * NQ) {
        int j = t - BATCH * NQ;
        float s, c;
        sincosf(0.5f * qp[j], &s, &c);
        g_cs_w[j] = make_float2(c, s);
    }
}

// Per-qubit single-qubit state after RY(n) then RX(n) then layer-0 RY(w):
//   u = RX(n) RY(n) |0> = (C^2 - i S^2, C S - i C S),  C=cos(n/2), S=sin(n/2)
//   v = RY(w) u  (real 2x2)
__device__ __forceinline__ void wire_vec(int b, int g, int q,
                                         float& v0r, float& v0i,
                                         float& v1r, float& v1i) {
    float2 cn = g_cs_noise[b * NQ + q];
    float C = cn.x, S = cn.y;
    float u0r = C * C, u0i = -S * S;
    float u1r = C * S, u1i = -(C * S);
    float2 w = g_cs_w[(g * QD + 0) * NQ + q];
    v0r = w.x * u0r - w.y * u1r;  v0i = w.x * u0i - w.y * u1i;
    v1r = w.y * u0r + w.x * u1r;  v1i = w.y * u0i + w.x * u1i;
}

// One warp per (batch, gen) circuit. Amp index i (10 bits): lane = bits 9..5,
// register index r = bits 4..0. PennyLane wire q <-> bit (9-q).
__global__ void __launch_bounds__(256) sim_kernel(float* __restrict__ out) {
    const unsigned FULL = 0xffffffffu;
    int gwarp = (blockIdx.x * blockDim.x + threadIdx.x) >> 5;
    int lane  = threadIdx.x & 31;
    int batch = gwarp >> 2;
    int gen   = gwarp & 3;

    float sre[32], sim_[32];

    // laneF = prod over wires 0..4 of v_w[bit], bit = (lane >> (4-w)) & 1
    float fr = 1.0f, fi = 0.0f;
    #pragma unroll
    for (int w = 0; w < 5; ++w) {
        float v0r, v0i, v1r, v1i;
        wire_vec(batch, gen, w, v0r, v0i, v1r, v1i);
        int bit = (lane >> (4 - w)) & 1;
        float pr = bit ? v1r : v0r;
        float pi = bit ? v1i : v0i;
        float nr = fr * pr - fi * pi;
        float ni = fr * pi + fi * pr;
        fr = nr; fi = ni;
    }

    // Build local 32-amp product table over wires 9..5 (bits 0..4), seeded by laneF
    sre[0] = fr; sim_[0] = fi;
    #pragma unroll
    for (int k = 0; k < 5; ++k) {
        int w = 9 - k;          // wire; bit k of r
        int len = 1 << k;
        float v0r, v0i, v1r, v1i;
        wire_vec(batch, gen, w, v0r, v0i, v1r, v1i);
        #pragma unroll
        for (int r = 0; r < (1 << k); ++r) {
            float ar = sre[r], ai = sim_[r];
            sre[r]        = ar * v0r - ai * v0i;
            sim_[r]       = ar * v0i + ai * v0r;
            sre[r + len]  = ar * v1r - ai * v1i;
            sim_[r + len] = ar * v1i + ai * v1r;
        }
    }

    // CZ-chain sign mask: bit r = parity of adjacent 1-1 pairs of i=(lane<<5)|r
    unsigned M = 0;
    #pragma unroll
    for (int r = 0; r < 32; ++r) {
        int i = (lane << 5) | r;
        unsigned p = __popc(i & (i >> 1) & 0x1FF) & 1u;
        M |= p << r;
    }

    auto apply_cz = [&]() {
        #pragma unroll
        for (int r = 0; r < 32; ++r) {
            unsigned sg = ((M >> r) & 1u) << 31;
            sre[r]  = __int_as_float(__float_as_int(sre[r])  ^ sg);
            sim_[r] = __int_as_float(__float_as_int(sim_[r]) ^ sg);
        }
    };

    apply_cz();  // layer 0's CZ (layer-0 RY already fused into init)

    for (int l = 1; l < QD; ++l) {
        float cw[NQ], sw[NQ];
        #pragma unroll
        for (int q = 0; q < NQ; ++q) {
            float2 t = g_cs_w[(gen * QD + l) * NQ + q];
            cw[q] = t.x; sw[q] = t.y;
        }
        #pragma unroll
        for (int q = 0; q < NQ; ++q) {
            if (q < 5) {
                // lane-bit gate (bit 9-q -> lane bit 4-q)
                int lb = 4 - q;
                int myBit = (lane >> lb) & 1;
                float ss = myBit ? sw[q] : -sw[q];
                float c = cw[q];
                #pragma unroll
                for (int r = 0; r < 32; ++r) {
                    float orr = __shfl_xor_sync(FULL, sre[r],  1 << lb);
                    float ori = __shfl_xor_sync(FULL, sim_[r], 1 << lb);
                    sre[r]  = fmaf(c, sre[r],  ss * orr);
                    sim_[r] = fmaf(c, sim_[r], ss * ori);
                }
            } else {
                // register-bit gate, m = 1 << (9-q)
                const int m = 1 << (9 - q);
                float c = cw[q], s = sw[q];
                #pragma unroll
                for (int r = 0; r < 32; ++r) {
                    if (r & m) continue;
                    int r1 = r | m;
                    float a0r = sre[r],  a0i = sim_[r];
                    float a1r = sre[r1], a1i = sim_[r1];
                    sre[r]   = fmaf(c, a0r, -s * a1r);
                    sim_[r]  = fmaf(c, a0i, -s * a1i);
                    sre[r1]  = fmaf(s, a0r,  c * a1r);
                    sim_[r1] = fmaf(s, a0i,  c * a1i);
                }
            }
        }
        apply_cz();
    }

    // Expectations: <X_q> = sum_i Re(conj(a_i) * a_{i ^ bit(9-q)})
    int obase = batch * (NGEN * NQ) + gen * NQ;
    #pragma unroll
    for (int q = 0; q < NQ; ++q) {
        float acc = 0.0f;
        if (q < 5) {
            int lb = 4 - q;
            #pragma unroll
            for (int r = 0; r < 32; ++r) {
                float orr = __shfl_xor_sync(FULL, sre[r],  1 << lb);
                float ori = __shfl_xor_sync(FULL, sim_[r], 1 << lb);
                acc = fmaf(sre[r],  orr, acc);
                acc = fmaf(sim_[r], ori, acc);
            }
        } else {
            const int m = 1 << (9 - q);
            #pragma unroll
            for (int r = 0; r < 32; ++r) {
                acc = fmaf(sre[r],  sre[r ^ m],  acc);
                acc = fmaf(sim_[r], sim_[r ^ m], acc);
            }
        }
        #pragma unroll
        for (int o = 16; o > 0; o >>= 1)
            acc += __shfl_xor_sync(FULL, acc, o);
        if (lane == 0) out[obase + q] = acc;
    }
}

extern "C" void kernel_launch(void* const* d_in, const int* in_sizes, int n_in,
                              void* d_out, int out_size) {
    const float* noise = (const float*)d_in[0];     // (1024, 10)
    const float* qp    = (const float*)d_in[1];     // (4, 6, 10)
    float* out = (float*)d_out;                     // (1024, 40)

    int tot = BATCH * NQ + NGEN * QD * NQ;
    prep_kernel<<<(tot + 255) / 256, 256>>>(noise, qp);

    // 4096 circuits, one warp each; 8 warps/block -> 512 blocks
    sim_kernel<<<(BATCH * NGEN * 32) / 256, 256>>>(out);
}

// round 4
// speedup vs baseline: 1.2130x; 1.2130x over previous
#include <cuda_runtime.h>

#define NQ 10
#define NGEN 4
#define QD 6
#define BATCH 1024

typedef unsigned long long ull;

// Precomputed (cos(a/2), sin(a/2)) tables
__device__ float2 g_cs_noise[BATCH * NQ];
__device__ float2 g_cs_w[NGEN * QD * NQ];

__global__ void prep_kernel(const float* __restrict__ noise,
                            const float* __restrict__ qp) {
    int t = blockIdx.x * blockDim.x + threadIdx.x;
    if (t < BATCH * NQ) {
        float s, c;
        sincosf(0.5f * noise[t], &s, &c);
        g_cs_noise[t] = make_float2(c, s);
    } else if (t < BATCH * NQ + NGEN * QD * NQ) {
        int j = t - BATCH * NQ;
        float s, c;
        sincosf(0.5f * qp[j], &s, &c);
        g_cs_w[j] = make_float2(c, s);
    }
}

// ---- packed f32x2 helpers (re in lo, im in hi) ----
__device__ __forceinline__ ull pk(float lo, float hi) {
    ull r; asm("mov.b64 %0, {%1, %2};" : "=l"(r) : "f"(lo), "f"(hi)); return r;
}
__device__ __forceinline__ void upk(ull v, float& lo, float& hi) {
    asm("mov.b64 {%0, %1}, %2;" : "=f"(lo), "=f"(hi) : "l"(v));
}
__device__ __forceinline__ ull fma2(ull a, ull b, ull c) {
    ull d; asm("fma.rn.f32x2 %0, %1, %2, %3;" : "=l"(d) : "l"(a), "l"(b), "l"(c)); return d;
}
__device__ __forceinline__ ull mul2(ull a, ull b) {
    ull d; asm("mul.rn.f32x2 %0, %1, %2;" : "=l"(d) : "l"(a), "l"(b)); return d;
}

// Per-qubit single-qubit state after RY(n) then RX(n) then layer-0 RY(w):
//   u = RX(n) RY(n) |0> = (C^2 - i S^2, C S - i C S),  C=cos(n/2), S=sin(n/2)
//   v = RY(w) u  (real 2x2)
__device__ __forceinline__ void wire_vec(int b, int g, int q,
                                         float& v0r, float& v0i,
                                         float& v1r, float& v1i) {
    float2 cn = g_cs_noise[b * NQ + q];
    float C = cn.x, S = cn.y;
    float u0r = C * C, u0i = -S * S;
    float u1r = C * S, u1i = -(C * S);
    float2 w = g_cs_w[(g * QD + 0) * NQ + q];
    v0r = w.x * u0r - w.y * u1r;  v0i = w.x * u0i - w.y * u1i;
    v1r = w.y * u0r + w.x * u1r;  v1i = w.y * u0i + w.x * u1i;
}

// One warp per (batch, gen) circuit. Amp index i (10 bits): lane = bits 9..5,
// register index r = bits 4..0. PennyLane wire q <-> bit (9-q).
__global__ void __launch_bounds__(256) sim_kernel(float* __restrict__ out) {
    const unsigned FULL = 0xffffffffu;
    int gwarp = (blockIdx.x * blockDim.x + threadIdx.x) >> 5;
    int lane  = threadIdx.x & 31;
    int batch = gwarp >> 2;
    int gen   = gwarp & 3;

    ull S[32];  // packed (re, im) per amplitude

    // laneF = prod over wires 0..4 of v_w[bit], bit = (lane >> (4-w)) & 1
    float fr = 1.0f, fi = 0.0f;
    #pragma unroll
    for (int w = 0; w < 5; ++w) {
        float v0r, v0i, v1r, v1i;
        wire_vec(batch, gen, w, v0r, v0i, v1r, v1i);
        int bit = (lane >> (4 - w)) & 1;
        float pr = bit ? v1r : v0r;
        float pi = bit ? v1i : v0i;
        float nr = fr * pr - fi * pi;
        float ni = fr * pi + fi * pr;
        fr = nr; fi = ni;
    }

    // Build local 32-amp product table over wires 9..5 (bits 0..4 of r)
    S[0] = pk(fr, fi);
    #pragma unroll
    for (int k = 0; k < 5; ++k) {
        int w = 9 - k;
        int len = 1 << k;
        float v0r, v0i, v1r, v1i;
        wire_vec(batch, gen, w, v0r, v0i, v1r, v1i);
        #pragma unroll
        for (int r = 0; r < (1 << k); ++r) {
            float ar, ai; upk(S[r], ar, ai);
            S[r]       = pk(ar * v0r - ai * v0i, ar * v0i + ai * v0r);
            S[r + len] = pk(ar * v1r - ai * v1i, ar * v1i + ai * v1r);
        }
    }

    // CZ-chain sign mask via decomposition:
    //   bit r of M = parity(i & (i>>1) & 0x1FF), i = (lane<<5)|r
    //             = K(r) ^ p_lane ^ ((lane&1) & (r>>4))
    unsigned K = 0;
    #pragma unroll
    for (int r = 0; r < 32; ++r)
        K |= (unsigned)(__popc(r & (r >> 1)) & 1) << r;   // compile-time constant
    unsigned p_lane = __popc(lane & (lane >> 1)) & 1u;
    unsigned M = K ^ (p_lane ? 0xFFFFFFFFu : 0u) ^ ((lane & 1) ? 0xFFFF0000u : 0u);

    auto apply_cz = [&]() {
        #pragma unroll
        for (int r = 0; r < 32; ++r) {
            ull sg = ((M >> r) & 1u) ? 0x8000000080000000ull : 0ull;
            S[r] ^= sg;
        }
    };

    apply_cz();  // layer 0's CZ (layer-0 RY fused into init)

    for (int l = 1; l < QD; ++l) {
        float cw[NQ], sw[NQ];
        #pragma unroll
        for (int q = 0; q < NQ; ++q) {
            float2 t = g_cs_w[(gen * QD + l) * NQ + q];
            cw[q] = t.x; sw[q] = t.y;
        }
        #pragma unroll
        for (int q = 0; q < NQ; ++q) {
            if (q < 5) {
                // lane-bit gate (wire q -> lane bit 4-q)
                int lb = 4 - q;
                float ssn = ((lane >> lb) & 1) ? sw[q] : -sw[q];
                ull cc = pk(cw[q], cw[q]);
                ull s2 = pk(ssn, ssn);
                #pragma unroll
                for (int r = 0; r < 32; ++r) {
                    ull p = __shfl_xor_sync(FULL, S[r], 1 << lb);
                    S[r] = fma2(cc, S[r], mul2(s2, p));
                }
            } else {
                // register-bit gate, m = 1 << (9-q)
                const int m = 1 << (9 - q);
                ull cc = pk(cw[q], cw[q]);
                ull sp = pk(sw[q], sw[q]);
                ull sn = pk(-sw[q], -sw[q]);
                #pragma unroll
                for (int r = 0; r < 32; ++r) {
                    if (r & m) continue;
                    int r1 = r | m;
                    ull a0 = S[r], a1 = S[r1];
                    S[r]  = fma2(cc, a0, mul2(sn, a1));
                    S[r1] = fma2(cc, a1, mul2(sp, a0));
                }
            }
        }
        apply_cz();
    }

    // Expectations: <X_q> = sum_i Re(conj(a_i) * a_{i ^ bit(9-q)})
    int obase = batch * (NGEN * NQ) + gen * NQ;
    #pragma unroll
    for (int q = 0; q < NQ; ++q) {
        float acc = 0.0f;
        if (q < 5) {
            int lb = 4 - q;
            #pragma unroll
            for (int r = 0; r < 32; ++r) {
                ull p = __shfl_xor_sync(FULL, S[r], 1 << lb);
                float re, im, pre, pim;
                upk(S[r], re, im); upk(p, pre, pim);
                acc = fmaf(re, pre, acc);
                acc = fmaf(im, pim, acc);
            }
        } else {
            const int m = 1 << (9 - q);
            #pragma unroll
            for (int r = 0; r < 32; ++r) {
                float re, im, pre, pim;
                upk(S[r], re, im); upk(S[r ^ m], pre, pim);
                acc = fmaf(re, pre, acc);
                acc = fmaf(im, pim, acc);
            }
        }
        #pragma unroll
        for (int o = 16; o > 0; o >>= 1)
            acc += __shfl_xor_sync(FULL, acc, o);
        if (lane == 0) out[obase + q] = acc;
    }
}

extern "C" void kernel_launch(void* const* d_in, const int* in_sizes, int n_in,
                              void* d_out, int out_size) {
    const float* noise = (const float*)d_in[0];     // (1024, 10)
    const float* qp    = (const float*)d_in[1];     // (4, 6, 10)
    float* out = (float*)d_out;                     // (1024, 40)

    int tot = BATCH * NQ + NGEN * QD * NQ;
    prep_kernel<<<(tot + 255) / 256, 256>>>(noise, qp);

    // 4096 circuits, one warp each; 8 warps/block -> 512 blocks
    sim_kernel<<<(BATCH * NGEN * 32) / 256, 256>>>(out);
}

// round 5
// speedup vs baseline: 1.4228x; 1.1730x over previous
#include <cuda_runtime.h>

#define NQ 10
#define NGEN 4
#define QD 6
#define BATCH 1024

typedef unsigned long long ull;

// ---- packed f32x2 helpers (re in lo, im in hi) ----
__device__ __forceinline__ ull pk(float lo, float hi) {
    ull r; asm("mov.b64 %0, {%1, %2};" : "=l"(r) : "f"(lo), "f"(hi)); return r;
}
__device__ __forceinline__ void upk(ull v, float& lo, float& hi) {
    asm("mov.b64 {%0, %1}, %2;" : "=f"(lo), "=f"(hi) : "l"(v));
}
__device__ __forceinline__ ull fma2(ull a, ull b, ull c) {
    ull d; asm("fma.rn.f32x2 %0, %1, %2, %3;" : "=l"(d) : "l"(a), "l"(b), "l"(c)); return d;
}
__device__ __forceinline__ ull mul2(ull a, ull b) {
    ull d; asm("mul.rn.f32x2 %0, %1, %2;" : "=l"(d) : "l"(a), "l"(b)); return d;
}

// One warp per (batch, gen) circuit. Amp index i (10 bits): lane = bits 9..5,
// register index r = bits 4..0. PennyLane wire q <-> bit (9-q).
__global__ void __launch_bounds__(64, 10) sim_kernel(const float* __restrict__ noise,
                                                     const float* __restrict__ qp,
                                                     float* __restrict__ out) {
    const unsigned FULL = 0xffffffffu;
    int gwarp = blockIdx.x * 2 + (threadIdx.x >> 5);
    int lane  = threadIdx.x & 31;
    int batch = gwarp >> 2;
    int gen   = gwarp & 3;

    ull S[32];  // packed (re, im) per amplitude

    // ---- in-warp angle prep for init ----
    // lanes 0..9: sincos(noise[batch,q]/2); lanes 16..25: sincos(w[gen,0,q]/2)
    float c_my = 0.f, s_my = 0.f;
    {
        float ang = 0.f;
        if (lane < NQ)                 ang = noise[batch * NQ + lane];
        else if (lane >= 16 && lane < 16 + NQ)
                                       ang = qp[(gen * QD + 0) * NQ + (lane - 16)];
        sincosf(0.5f * ang, &s_my, &c_my);
    }

    // Per-wire init vector: u = RX(n)RY(n)|0> = (C^2 - i S^2, CS - i CS),
    // then layer-0 RY(w):  v = RY(w) u
    auto wire_vec = [&](int q, float& v0r, float& v0i, float& v1r, float& v1i) {
        float C  = __shfl_sync(FULL, c_my, q);
        float Sn = __shfl_sync(FULL, s_my, q);
        float wc = __shfl_sync(FULL, c_my, 16 + q);
        float ws = __shfl_sync(FULL, s_my, 16 + q);
        float u0r = C * C, u0i = -Sn * Sn;
        float u1r = C * Sn, u1i = -(C * Sn);
        v0r = wc * u0r - ws * u1r;  v0i = wc * u0i - ws * u1i;
        v1r = ws * u0r + wc * u1r;  v1i = ws * u0i + wc * u1i;
    };

    // laneF = prod over wires 0..4 of v_w[bit], bit = (lane >> (4-w)) & 1
    float fr = 1.0f, fi = 0.0f;
    #pragma unroll
    for (int w = 0; w < 5; ++w) {
        float v0r, v0i, v1r, v1i;
        wire_vec(w, v0r, v0i, v1r, v1i);
        int bit = (lane >> (4 - w)) & 1;
        float pr = bit ? v1r : v0r;
        float pi = bit ? v1i : v0i;
        float nr = fr * pr - fi * pi;
        float ni = fr * pi + fi * pr;
        fr = nr; fi = ni;
    }

    // Build local 32-amp product table over wires 9..5 (bits 0..4 of r)
    S[0] = pk(fr, fi);
    #pragma unroll
    for (int k = 0; k < 5; ++k) {
        int w = 9 - k;
        int len = 1 << k;
        float v0r, v0i, v1r, v1i;
        wire_vec(w, v0r, v0i, v1r, v1i);
        #pragma unroll
        for (int r = 0; r < (1 << k); ++r) {
            float ar, ai; upk(S[r], ar, ai);
            S[r]       = pk(ar * v0r - ai * v0i, ar * v0i + ai * v0r);
            S[r + len] = pk(ar * v1r - ai * v1i, ar * v1i + ai * v1r);
        }
    }

    // CZ-chain sign mask: bit r of M = K(r) ^ p_lane ^ ((lane&1) & (r>>4))
    unsigned K = 0;
    #pragma unroll
    for (int r = 0; r < 32; ++r)
        K |= (unsigned)(__popc(r & (r >> 1)) & 1) << r;   // compile-time constant
    unsigned p_lane = __popc(lane & (lane >> 1)) & 1u;
    unsigned M = K ^ (p_lane ? 0xFFFFFFFFu : 0u) ^ ((lane & 1) ? 0xFFFF0000u : 0u);

    auto apply_cz = [&]() {
        #pragma unroll
        for (int r = 0; r < 32; ++r) {
            ull sg = ((M >> r) & 1u) ? 0x8000000080000000ull : 0ull;
            S[r] ^= sg;
        }
    };

    apply_cz();  // layer 0's CZ (layer-0 RY fused into init)

    #pragma unroll 1
    for (int l = 1; l < QD; ++l) {
        // lanes 0..9 compute this layer's sincos; lanes 5..9 also the shear tan
        float lc = 0.f, ls = 0.f, lt = 0.f;
        if (lane < NQ) {
            float ang = qp[(gen * QD + l) * NQ + lane];
            sincosf(0.5f * ang, &ls, &lc);
            lt = __fdividef(ls, 1.0f + lc);   // tan(ang/4)
        }

        // register-bit gates first (wires 5..9), 3-shear form
        #pragma unroll
        for (int q = 5; q < NQ; ++q) {
            const int m = 1 << (9 - q);
            float t = __shfl_sync(FULL, lt, q);
            float s = __shfl_sync(FULL, ls, q);
            ull tn = pk(-t, -t);
            ull ss = pk(s, s);
            #pragma unroll
            for (int r = 0; r < 32; ++r) {
                if (r & m) continue;
                int r1 = r | m;
                ull u   = fma2(tn, S[r1], S[r]);   // a0 - t a1
                ull a1p = fma2(ss, u, S[r1]);      // a1 + s u
                S[r]  = fma2(tn, a1p, u);          // u - t a1'
                S[r1] = a1p;
            }
        }

        // lane-bit gates (wires 0..4)
        #pragma unroll
        for (int q = 0; q < 5; ++q) {
            int lb = 4 - q;
            float c = __shfl_sync(FULL, lc, q);
            float s = __shfl_sync(FULL, ls, q);
            float ssn = ((lane >> lb) & 1) ? s : -s;
            ull cc = pk(c, c);
            ull s2 = pk(ssn, ssn);
            #pragma unroll
            for (int r = 0; r < 32; ++r) {
                ull p = __shfl_xor_sync(FULL, S[r], 1 << lb);
                S[r] = fma2(cc, S[r], mul2(s2, p));
            }
        }

        apply_cz();
    }

    // Expectations: <X_q> = sum_i Re(conj(a_i) * a_{i ^ bit(9-q)})
    float acc[NQ];
    #pragma unroll
    for (int q = 0; q < NQ; ++q) {
        float a = 0.0f;
        if (q < 5) {
            int lb = 4 - q;
            #pragma unroll
            for (int r = 0; r < 32; ++r) {
                ull p = __shfl_xor_sync(FULL, S[r], 1 << lb);
                float re, im, pre, pim;
                upk(S[r], re, im); upk(p, pre, pim);
                a = fmaf(re, pre, a);
                a = fmaf(im, pim, a);
            }
        } else {
            const int m = 1 << (9 - q);
            #pragma unroll
            for (int r = 0; r < 32; ++r) {
                float re, im, pre, pim;
                upk(S[r], re, im); upk(S[r ^ m], pre, pim);
                a = fmaf(re, pre, a);
                a = fmaf(im, pim, a);
            }
        }
        acc[q] = a;
    }

    // packed pairwise butterfly reduction: 5 ull accs instead of 10 floats
    int obase = batch * (NGEN * NQ) + gen * NQ;
    #pragma unroll
    for (int k = 0; k < 5; ++k) {
        ull v = pk(acc[2 * k], acc[2 * k + 1]);
        #pragma unroll
        for (int o = 16; o > 0; o >>= 1) {
            ull p = __shfl_xor_sync(FULL, v, o);
            asm("add.rn.f32x2 %0, %1, %2;" : "=l"(v) : "l"(v), "l"(p));
        }
        if (lane == 0)
            *reinterpret_cast<float2*>(out + obase + 2 * k) =
                *reinterpret_cast<float2*>(&v);
    }
}

extern "C" void kernel_launch(void* const* d_in, const int* in_sizes, int n_in,
                              void* d_out, int out_size) {
    const float* noise = (const float*)d_in[0];     // (1024, 10)
    const float* qp    = (const float*)d_in[1];     // (4, 6, 10)
    float* out = (float*)d_out;                     // (1024, 40)

    // 4096 circuits, one warp each; 2 warps/block -> 2048 blocks
    sim_kernel<<<(BATCH * NGEN) / 2, 64>>>(noise, qp, out);
}